// round 8
// baseline (speedup 1.0000x reference)
#include <cuda_runtime.h>
#include <math.h>

#define B_      32
#define N_      325
#define L_      12
#define D_      128
#define H_      8
#define DK      16
#define BN      (B_*N_)        // 10400
#define ROWS    (BN*L_)        // 124800
#define MAXREL  11
#define LL      (L_*L_)        // 144
#define HLL     (H_*LL)        // 1152
#define PITCH   132
#define TT      4              // (b,n) tiles per fused block
#define MROWS   (TT*L_)        // 48
#define NBF     (BN/TT)        // 2600
#define MO      32             // out_kernel row-tile
#define NBO     (ROWS/MO)      // 3900

typedef unsigned int u32t;

// ---- static device scratch ----
__device__ __align__(16) u32t  g_Wfrag[4][D_*D_];   // tf32 weights in B-fragment order
__device__ __align__(16) float g_K2[LL*DK];
__device__ __align__(16) float g_V2[LL*DK];
__device__ __align__(16) float g_ctx[(size_t)ROWS*D_];
__device__ __align__(16) float g_psum[(size_t)BN*D_];    // [bn][c]
__device__ __align__(16) float g_psumsq[(size_t)BN*D_];  // [bn][c]
__device__ float g_scale[D_];
__device__ float g_shift[D_];

__device__ __forceinline__ u32t to_tf32(float x) {
    u32t t; asm("cvt.rna.tf32.f32 %0, %1;" : "=r"(t) : "f"(x)); return t;
}
__device__ __forceinline__ void mma_tf32(float c[4], const u32t a[4], u32t b0, u32t b1) {
    asm volatile("mma.sync.aligned.m16n8k8.row.col.f32.tf32.tf32.f32 "
                 "{%0,%1,%2,%3}, {%4,%5,%6,%7}, {%8,%9}, {%0,%1,%2,%3};"
                 : "+f"(c[0]), "+f"(c[1]), "+f"(c[2]), "+f"(c[3])
                 : "r"(a[0]), "r"(a[1]), "r"(a[2]), "r"(a[3]), "r"(b0), "r"(b1));
}

// ---------------------------------------------------------------------------
// Kernel 1: weight-norm -> tf32 B-fragment layout; rel-position tables
// ---------------------------------------------------------------------------
__global__ void prep_kernel(const float* __restrict__ wq_v, const float* __restrict__ wq_g,
                            const float* __restrict__ wk_v, const float* __restrict__ wk_g,
                            const float* __restrict__ wv_v, const float* __restrict__ wv_g,
                            const float* __restrict__ fc_v, const float* __restrict__ fc_g,
                            const float* __restrict__ rel_k, const float* __restrict__ rel_v) {
    int blk = blockIdx.x;
    if (blk < 4) {
        const float* v; const float* g;
        switch (blk) {
            case 0: v = wq_v; g = wq_g; break;
            case 1: v = wk_v; g = wk_g; break;
            case 2: v = wv_v; g = wv_g; break;
            default: v = fc_v; g = fc_g; break;
        }
        __shared__ float s_sc[D_];
        int r = threadIdx.x;
        float s = 0.f;
        for (int d = 0; d < D_; d++) { float x = v[r*D_ + d]; s += x*x; }
        s_sc[r] = g[r] * rsqrtf(s);
        __syncthreads();
        for (int idx = threadIdx.x; idx < D_*D_; idx += 128) {
            int rr   = idx & 1;
            int lane = (idx >> 1) & 31;
            int nn   = (idx >> 6) & 15;
            int kk   = idx >> 10;
            int k = kk*8 + (lane & 3) + 4*rr;
            int n = nn*8 + (lane >> 2);
            g_Wfrag[blk][idx] = to_tf32(v[n*D_ + k] * s_sc[n]);
        }
    } else {
        for (int t = threadIdx.x; t < LL; t += blockDim.x) {
            int q = t / L_, k = t % L_;
            int dist = max(-MAXREL, min(MAXREL, k - q));
            int row = dist + MAXREL;
            for (int d = 0; d < DK; d++) {
                g_K2[t*DK + d] = rel_k[row*DK + d];
                g_V2[t*DK + d] = rel_v[row*DK + d];
            }
        }
    }
}

__device__ __forceinline__ void store_warp(float* __restrict__ dst,
                                           int mw, int nw, int lane, const float acc[8][4]) {
    const int g = lane >> 2, tig = lane & 3;
    const int row = mw*16 + g;
    const int colb = nw*64 + 2*tig;
    #pragma unroll
    for (int nn = 0; nn < 8; nn++) {
        *(float2*)(dst + row*PITCH + colb + nn*8)     = make_float2(acc[nn][0], acc[nn][1]);
        *(float2*)(dst + (row+8)*PITCH + colb + nn*8) = make_float2(acc[nn][2], acc[nn][3]);
    }
}

__device__ __forceinline__ void stage_tf32(const float* __restrict__ src, float* __restrict__ dst,
                                           int tid) {
    const float4* s4 = (const float4*)src;
    for (int i = tid; i < MROWS*32; i += 256) {
        float4 x = s4[i];
        int row = i >> 5, c4 = i & 31;
        uint4 t;
        t.x = to_tf32(x.x); t.y = to_tf32(x.y); t.z = to_tf32(x.z); t.w = to_tf32(x.w);
        ((uint4*)((u32t*)dst + row*PITCH))[c4] = t;
    }
}

// ---------------------------------------------------------------------------
// In-place 48x128x128 GEMM phase with smem-staged weight chunks (16 KB x 4).
// Each MMA warp (warp<6) touches only its own 16-row slice -> in-place safe.
// ---------------------------------------------------------------------------
__device__ __forceinline__ void gemm_phase(float* __restrict__ buf,
                                           const u32t* __restrict__ Wg,
                                           u32t* __restrict__ s_w,
                                           int tid, int warp, int lane, int mw, int nw) {
    float acc[8][4];
    #pragma unroll
    for (int nn = 0; nn < 8; nn++)
        #pragma unroll
        for (int q = 0; q < 4; q++) acc[nn][q] = 0.f;

    const int g = lane >> 2, tig = lane & 3;
    #pragma unroll
    for (int c = 0; c < 4; c++) {
        __syncthreads();                       // s_w free (prev chunk consumed)
        const uint4* src = (const uint4*)(Wg + c*4096);
        uint4* dstw = (uint4*)s_w;
        #pragma unroll
        for (int i = 0; i < 4; i++) dstw[tid + i*256] = src[tid + i*256];
        __syncthreads();                       // chunk ready
        if (warp < 6) {
            #pragma unroll
            for (int k2 = 0; k2 < 4; k2++) {
                const int kk = c*4 + k2;
                u32t a[4];
                const u32t* base = (const u32t*)buf + (mw*16 + g)*PITCH + kk*8 + tig;
                a[0] = base[0];
                a[1] = base[8*PITCH];
                a[2] = base[4];
                a[3] = base[8*PITCH + 4];
                const uint2* bp2 = (const uint2*)(s_w + (k2*16 + nw*8)*64) + lane;
                #pragma unroll
                for (int nn = 0; nn < 8; nn++) {
                    uint2 b = bp2[nn*32];
                    mma_tf32(acc[nn], a, b.x, b.y);
                }
            }
        }
    }
    __syncthreads();                           // all reads of buf complete
    if (warp < 6) store_warp(buf, mw, nw, lane, acc);
}

// ---------------------------------------------------------------------------
// Kernel 2: FUSED projections + attention middle. 4 (b,n) tiles per block.
// ---------------------------------------------------------------------------
__global__ __launch_bounds__(256, 2) void fused_kernel(const float* __restrict__ inQ,
                                                       const float* __restrict__ inK,
                                                       const float* __restrict__ inV,
                                                       const float* __restrict__ w1,
                                                       const float* __restrict__ w2,
                                                       float* __restrict__ attn_out) {
    extern __shared__ __align__(16) float sm[];
    float* sA   = sm;            // Xq tf32 -> Q fp32 -> s_at2
    float* sB   = sm + 6336;     // Xk tf32 -> K fp32
    float* sC   = sm + 12672;    // Xv tf32 -> V fp32
    float* s_at = sm + 19008;    // 4608 floats; first 4096 aliased as weight chunk
    float* s_k2 = sm + 23616;    // 2304
    float* s_v2 = sm + 25920;    // 2304
    float* s_w1 = sm + 28224;    // 64
    float* s_w2 = sm + 28288;    // 64
    float* s_at2 = sA;
    u32t*  s_w  = (u32t*)s_at;   // 16 KB weight chunk staging (dead until scores)

    const int tid  = threadIdx.x;
    const int lane = tid & 31, warp = tid >> 5;
    const int mw = warp >> 1, nw = warp & 1;    // valid for warp < 6
    const int bn0 = blockIdx.x * TT;
    const size_t gbase = (size_t)bn0 * (L_*D_);

    // ---- S0: stage all three inputs + tables ----
    stage_tf32(inQ + gbase, sA, tid);
    stage_tf32(inK + gbase, sB, tid);
    stage_tf32(inV + gbase, sC, tid);
    for (int t = tid; t < LL; t += 256) {
        const float4* sk = (const float4*)(g_K2 + t*DK);
        const float4* sv = (const float4*)(g_V2 + t*DK);
        #pragma unroll
        for (int j = 0; j < 4; j++) {
            ((float4*)(s_k2 + t*DK))[j] = sk[j];
            ((float4*)(s_v2 + t*DK))[j] = sv[j];
        }
    }
    if (tid < 64) { s_w1[tid] = w1[tid]; s_w2[tid] = w2[tid]; }
    // (gemm_phase starts with __syncthreads)

    gemm_phase(sA, g_Wfrag[0], s_w, tid, warp, lane, mw, nw);
    gemm_phase(sB, g_Wfrag[1], s_w, tid, warp, lane, mw, nw);
    gemm_phase(sC, g_Wfrag[2], s_w, tid, warp, lane, mw, nw);
    __syncthreads();

    // ---- scores + w1 mix + leaky relu ----
    for (int idx = tid; idx < TT*LL; idx += 256) {
        int t = idx / LL, rem = idx - t*LL;
        int i = rem / L_, j = rem - i*L_;
        const float* qrow = sA + (t*L_ + i)*PITCH;
        const float* krow = sB + (t*L_ + j)*PITCH;
        const float4* k2 = (const float4*)(s_k2 + rem*DK);
        float4 r0 = k2[0], r1 = k2[1], r2 = k2[2], r3 = k2[3];
        float sc[H_];
        #pragma unroll
        for (int h = 0; h < H_; h++) {
            const float4* q4 = (const float4*)(qrow + h*DK);
            const float4* k4 = (const float4*)(krow + h*DK);
            float4 q0 = q4[0], q1 = q4[1], q2 = q4[2], q3 = q4[3];
            float4 k0 = k4[0], k1 = k4[1], k2v = k4[2], k3 = k4[3];
            float s = 0.f;
            s += q0.x*(k0.x+r0.x) + q0.y*(k0.y+r0.y) + q0.z*(k0.z+r0.z) + q0.w*(k0.w+r0.w);
            s += q1.x*(k1.x+r1.x) + q1.y*(k1.y+r1.y) + q1.z*(k1.z+r1.z) + q1.w*(k1.w+r1.w);
            s += q2.x*(k2v.x+r2.x) + q2.y*(k2v.y+r2.y) + q2.z*(k2v.z+r2.z) + q2.w*(k2v.w+r2.w);
            s += q3.x*(k3.x+r3.x) + q3.y*(k3.y+r3.y) + q3.z*(k3.z+r3.z) + q3.w*(k3.w+r3.w);
            sc[h] = s * 0.25f;
        }
        #pragma unroll
        for (int g = 0; g < H_; g++) {
            float s = 0.f;
            #pragma unroll
            for (int h = 0; h < H_; h++) s += sc[h] * s_w1[h*H_ + g];
            s_at[t*HLL + g*LL + rem] = (s > 0.f) ? s : 0.2f * s;
        }
    }
    __syncthreads();

    // ---- softmax over k: TT*96 rows of 12 ----
    for (int rowid = tid; rowid < TT*H_*L_; rowid += 256) {
        float* row = s_at + rowid * L_;
        float mx = row[0];
        #pragma unroll
        for (int j = 1; j < L_; j++) mx = fmaxf(mx, row[j]);
        float sum = 0.f;
        #pragma unroll
        for (int j = 0; j < L_; j++) { float e = __expf(row[j] - mx); row[j] = e; sum += e; }
        float inv = 1.f / sum;
        #pragma unroll
        for (int j = 0; j < L_; j++) row[j] *= inv;
    }
    __syncthreads();

    // ---- w2 mix -> s_at2 (A region; Q dead) + attn_ret write ----
    for (int idx = tid; idx < TT*LL; idx += 256) {
        int t = idx / LL, rem = idx - t*LL;
        int i = rem / L_, j = rem - i*L_;
        float a[H_];
        #pragma unroll
        for (int h = 0; h < H_; h++) a[h] = s_at[t*HLL + h*LL + rem];
        #pragma unroll
        for (int g = 0; g < H_; g++) {
            float s = 0.f;
            #pragma unroll
            for (int h = 0; h < H_; h++) s += a[h] * s_w2[h*H_ + g];
            s_at2[t*HLL + g*LL + rem] = s;
            attn_out[(size_t)i * ((size_t)BN*96) + (size_t)(bn0+t)*96 + g*L_ + j] = s;
        }
    }
    __syncthreads();

    // ---- context + BN partials (coalesced [bn][c] layout) ----
    {
        const int c = tid & 127;
        const int h = c >> 4, d = c & 15;
        #pragma unroll
        for (int tt = 0; tt < 2; tt++) {
            const int t = (tid >> 7) + 2*tt;
            float vj[L_];
            #pragma unroll
            for (int j = 0; j < L_; j++) vj[j] = sC[(t*L_ + j)*PITCH + c];
            const float* at = s_at2 + t*HLL + h*LL;
            float* ctxp = g_ctx + (size_t)(bn0 + t) * (L_*D_);
            float sum = 0.f, sq = 0.f;
            #pragma unroll
            for (int i = 0; i < L_; i++) {
                float a2 = 0.f;
                #pragma unroll
                for (int j = 0; j < L_; j++)
                    a2 = fmaf(at[i*L_ + j], vj[j] + s_v2[(i*L_ + j)*DK + d], a2);
                ctxp[i*D_ + c] = a2;
                sum += a2;
                sq = fmaf(a2, a2, sq);
            }
            g_psum  [(size_t)(bn0 + t)*D_ + c] = sum;
            g_psumsq[(size_t)(bn0 + t)*D_ + c] = sq;
        }
    }
}

// ---------------------------------------------------------------------------
// Kernel 3: finalize BN stats. 32 blocks, block b -> channels [4b, 4b+4).
// ---------------------------------------------------------------------------
__global__ void stats_kernel(const float* __restrict__ gamma, const float* __restrict__ beta) {
    __shared__ float red[8][256];
    const int tid = threadIdx.x;
    const int cb  = blockIdx.x * 4;
    float4 s  = make_float4(0.f, 0.f, 0.f, 0.f);
    float4 sq = make_float4(0.f, 0.f, 0.f, 0.f);
    for (int bn = tid; bn < BN; bn += 256) {
        float4 p = *(const float4*)(g_psum   + (size_t)bn*D_ + cb);
        float4 q = *(const float4*)(g_psumsq + (size_t)bn*D_ + cb);
        s.x += p.x; s.y += p.y; s.z += p.z; s.w += p.w;
        sq.x += q.x; sq.y += q.y; sq.z += q.z; sq.w += q.w;
    }
    red[0][tid] = s.x;  red[1][tid] = s.y;  red[2][tid] = s.z;  red[3][tid] = s.w;
    red[4][tid] = sq.x; red[5][tid] = sq.y; red[6][tid] = sq.z; red[7][tid] = sq.w;
    __syncthreads();
    for (int st = 128; st > 0; st >>= 1) {
        if (tid < st) {
            #pragma unroll
            for (int j = 0; j < 8; j++) red[j][tid] += red[j][tid + st];
        }
        __syncthreads();
    }
    if (tid < 4) {
        const float invN = 1.f / (float)ROWS;
        int c = cb + tid;
        float mean = red[tid][0] * invN;
        float var  = red[tid + 4][0] * invN - mean*mean;
        float sc = rsqrtf(var + 1e-5f) * gamma[c];
        g_scale[c] = sc;
        g_shift[c] = beta[c] - mean * sc;
    }
}

// ---------------------------------------------------------------------------
// Kernel 4: BN-apply + fc GEMM + ReLU + residual. M=32 tiles, grid=NBO.
// 8 warps: mw = warp&1 (m16x2), nw = warp>>1 (n32x4).
// ---------------------------------------------------------------------------
__global__ __launch_bounds__(256, 4) void out_kernel(const float* __restrict__ inV,
                                                     float* __restrict__ out) {
    __shared__ __align__(16) u32t s_x[MO*PITCH];
    __shared__ float s_scale[D_], s_shift[D_];
    const int tid = threadIdx.x;
    const size_t base = (size_t)blockIdx.x * MO * D_;

    if (tid < D_) { s_scale[tid] = g_scale[tid]; s_shift[tid] = g_shift[tid]; }
    __syncthreads();

    const float4* ctx4 = (const float4*)(g_ctx + base);
    const float4* sc4 = (const float4*)s_scale;
    const float4* sh4 = (const float4*)s_shift;
    for (int i = tid; i < MO*32; i += 256) {
        float4 x = ctx4[i];
        float4 sc = sc4[i & 31], sh = sh4[i & 31];
        int row = i >> 5, c4 = i & 31;
        uint4 t;
        t.x = to_tf32(x.x*sc.x + sh.x);
        t.y = to_tf32(x.y*sc.y + sh.y);
        t.z = to_tf32(x.z*sc.z + sh.z);
        t.w = to_tf32(x.w*sc.w + sh.w);
        ((uint4*)(s_x + row*PITCH))[c4] = t;
    }
    __syncthreads();

    const int lane = tid & 31, warp = tid >> 5;
    const int mw = warp & 1, nw = warp >> 1;
    const int g = lane >> 2, tig = lane & 3;

    float acc[4][4];
    #pragma unroll
    for (int nn = 0; nn < 4; nn++)
        #pragma unroll
        for (int q = 0; q < 4; q++) acc[nn][q] = 0.f;

    #pragma unroll 4
    for (int kk = 0; kk < 16; kk++) {
        u32t a[4];
        const u32t* abase = s_x + (mw*16 + g)*PITCH + kk*8 + tig;
        a[0] = abase[0];
        a[1] = abase[8*PITCH];
        a[2] = abase[4];
        a[3] = abase[8*PITCH + 4];
        const uint2* bp2 = (const uint2*)(g_Wfrag[3] + (kk*16 + nw*4)*64) + lane;
        #pragma unroll
        for (int nn = 0; nn < 4; nn++) {
            uint2 b = bp2[nn*32];
            mma_tf32(acc[nn], a, b.x, b.y);
        }
    }

    const float* vin = inV + base;
    float* dst = out + base;
    const int row = mw*16 + g;
    const int colb = nw*32 + 2*tig;
    #pragma unroll
    for (int nn = 0; nn < 4; nn++) {
        int col = colb + nn*8;
        float2 v0 = *(const float2*)(vin + (size_t)row*D_ + col);
        float2 v1 = *(const float2*)(vin + (size_t)(row+8)*D_ + col);
        float2 o0, o1;
        o0.x = fmaxf(acc[nn][0], 0.f) + v0.x;
        o0.y = fmaxf(acc[nn][1], 0.f) + v0.y;
        o1.x = fmaxf(acc[nn][2], 0.f) + v1.x;
        o1.y = fmaxf(acc[nn][3], 0.f) + v1.y;
        *(float2*)(dst + (size_t)row*D_ + col)     = o0;
        *(float2*)(dst + (size_t)(row+8)*D_ + col) = o1;
    }
}

// ---------------------------------------------------------------------------
extern "C" void kernel_launch(void* const* d_in, const int* in_sizes, int n_in,
                              void* d_out, int out_size) {
    const float* inQ   = (const float*)d_in[0];
    const float* inK   = (const float*)d_in[1];
    const float* inV   = (const float*)d_in[2];
    const float* wq_v  = (const float*)d_in[3];
    const float* wq_g  = (const float*)d_in[4];
    const float* wk_v  = (const float*)d_in[5];
    const float* wk_g  = (const float*)d_in[6];
    const float* wv_v  = (const float*)d_in[7];
    const float* wv_g  = (const float*)d_in[8];
    const float* fc_v  = (const float*)d_in[9];
    const float* fc_g  = (const float*)d_in[10];
    const float* rel_k = (const float*)d_in[11];
    const float* rel_v = (const float*)d_in[12];
    const float* w1    = (const float*)d_in[13];
    const float* w2    = (const float*)d_in[14];
    const float* gamma = (const float*)d_in[15];
    const float* beta  = (const float*)d_in[16];

    float* out      = (float*)d_out;
    float* attn_out = out + (size_t)ROWS * D_;

    const int fused_smem = 28352 * (int)sizeof(float);   // 113,408 B
    cudaFuncSetAttribute(fused_kernel, cudaFuncAttributeMaxDynamicSharedMemorySize, fused_smem);

    prep_kernel<<<5, 128>>>(wq_v, wq_g, wk_v, wk_g, wv_v, wv_g, fc_v, fc_g, rel_k, rel_v);
    fused_kernel<<<NBF, 256, fused_smem>>>(inQ, inK, inV, w1, w2, attn_out);
    stats_kernel<<<32, 256>>>(gamma, beta);
    out_kernel<<<NBO, 256>>>(inV, out);
}

// round 9
// speedup vs baseline: 1.0850x; 1.0850x over previous
#include <cuda_runtime.h>
#include <math.h>

#define B_      32
#define N_      325
#define L_      12
#define D_      128
#define H_      8
#define DK      16
#define BN      (B_*N_)        // 10400
#define ROWS    (BN*L_)        // 124800
#define MAXREL  11
#define LL      (L_*L_)        // 144
#define HLL     (H_*LL)        // 1152
#define PITCH   132
#define TT      4              // (b,n) tiles per fused block
#define MROWS   (TT*L_)        // 48
#define NBF     (BN/TT)        // 2600
#define MO      32             // out_kernel row-tile
#define NBO     (ROWS/MO)      // 3900

typedef unsigned int u32t;

// ---- static device scratch ----
__device__ __align__(16) u32t  g_Wfrag[4][D_*D_];   // tf32 weights in B-fragment order
__device__ __align__(16) float g_K2[LL*DK];
__device__ __align__(16) float g_V2[LL*DK];
__device__ __align__(16) float g_ctx[(size_t)ROWS*D_];
__device__ __align__(16) float g_psum[(size_t)BN*D_];    // [bn][c]
__device__ __align__(16) float g_psumsq[(size_t)BN*D_];  // [bn][c]
__device__ float g_scale[D_];
__device__ float g_shift[D_];

__device__ __forceinline__ u32t to_tf32(float x) {
    u32t t; asm("cvt.rna.tf32.f32 %0, %1;" : "=r"(t) : "f"(x)); return t;
}
__device__ __forceinline__ void mma_tf32(float c[4], const u32t a[4], u32t b0, u32t b1) {
    asm volatile("mma.sync.aligned.m16n8k8.row.col.f32.tf32.tf32.f32 "
                 "{%0,%1,%2,%3}, {%4,%5,%6,%7}, {%8,%9}, {%0,%1,%2,%3};"
                 : "+f"(c[0]), "+f"(c[1]), "+f"(c[2]), "+f"(c[3])
                 : "r"(a[0]), "r"(a[1]), "r"(a[2]), "r"(a[3]), "r"(b0), "r"(b1));
}

// ---------------------------------------------------------------------------
// Kernel 1: weight-norm -> tf32 B-fragment layout; rel-position tables
// ---------------------------------------------------------------------------
__global__ void prep_kernel(const float* __restrict__ wq_v, const float* __restrict__ wq_g,
                            const float* __restrict__ wk_v, const float* __restrict__ wk_g,
                            const float* __restrict__ wv_v, const float* __restrict__ wv_g,
                            const float* __restrict__ fc_v, const float* __restrict__ fc_g,
                            const float* __restrict__ rel_k, const float* __restrict__ rel_v) {
    int blk = blockIdx.x;
    if (blk < 4) {
        const float* v; const float* g;
        switch (blk) {
            case 0: v = wq_v; g = wq_g; break;
            case 1: v = wk_v; g = wk_g; break;
            case 2: v = wv_v; g = wv_g; break;
            default: v = fc_v; g = fc_g; break;
        }
        __shared__ float s_sc[D_];
        int r = threadIdx.x;
        float s = 0.f;
        for (int d = 0; d < D_; d++) { float x = v[r*D_ + d]; s += x*x; }
        s_sc[r] = g[r] * rsqrtf(s);
        __syncthreads();
        for (int idx = threadIdx.x; idx < D_*D_; idx += 128) {
            int rr   = idx & 1;
            int lane = (idx >> 1) & 31;
            int nn   = (idx >> 6) & 15;
            int kk   = idx >> 10;
            int k = kk*8 + (lane & 3) + 4*rr;
            int n = nn*8 + (lane >> 2);
            g_Wfrag[blk][idx] = to_tf32(v[n*D_ + k] * s_sc[n]);
        }
    } else {
        for (int t = threadIdx.x; t < LL; t += blockDim.x) {
            int q = t / L_, k = t % L_;
            int dist = max(-MAXREL, min(MAXREL, k - q));
            int row = dist + MAXREL;
            for (int d = 0; d < DK; d++) {
                g_K2[t*DK + d] = rel_k[row*DK + d];
                g_V2[t*DK + d] = rel_v[row*DK + d];
            }
        }
    }
}

// ---------------------------------------------------------------------------
// m16n64 warp-MMA over K=128, uint2 B-fragment loads (1 LDG.64 per pair)
// ---------------------------------------------------------------------------
__device__ __forceinline__ void mma_warp(const u32t* __restrict__ s_x,
                                         const u32t* __restrict__ Wf,
                                         int mw, int nw, int lane, float acc[8][4]) {
    const int g = lane >> 2, tig = lane & 3;
    #pragma unroll
    for (int nn = 0; nn < 8; nn++)
        #pragma unroll
        for (int q = 0; q < 4; q++) acc[nn][q] = 0.f;
    #pragma unroll 4
    for (int kk = 0; kk < 16; kk++) {
        u32t a[4];
        const u32t* base = s_x + (mw*16 + g)*PITCH + kk*8 + tig;
        a[0] = base[0];
        a[1] = base[8*PITCH];
        a[2] = base[4];
        a[3] = base[8*PITCH + 4];
        const uint2* bp2 = (const uint2*)(Wf + (kk*16 + nw*8)*64) + lane;
        #pragma unroll
        for (int nn = 0; nn < 8; nn++) {
            uint2 b = bp2[nn*32];
            mma_tf32(acc[nn], a, b.x, b.y);
        }
    }
}
__device__ __forceinline__ void store_warp(float* __restrict__ dst,
                                           int mw, int nw, int lane, const float acc[8][4]) {
    const int g = lane >> 2, tig = lane & 3;
    const int row = mw*16 + g;
    const int colb = nw*64 + 2*tig;
    #pragma unroll
    for (int nn = 0; nn < 8; nn++) {
        *(float2*)(dst + row*PITCH + colb + nn*8)     = make_float2(acc[nn][0], acc[nn][1]);
        *(float2*)(dst + (row+8)*PITCH + colb + nn*8) = make_float2(acc[nn][2], acc[nn][3]);
    }
}

__device__ __forceinline__ void stage_tf32(const float* __restrict__ src, float* __restrict__ dst,
                                           int tid) {
    const float4* s4 = (const float4*)src;
    for (int i = tid; i < MROWS*32; i += 256) {
        float4 x = s4[i];
        int row = i >> 5, c4 = i & 31;
        uint4 t;
        t.x = to_tf32(x.x); t.y = to_tf32(x.y); t.z = to_tf32(x.z); t.w = to_tf32(x.w);
        ((uint4*)((u32t*)dst + row*PITCH))[c4] = t;
    }
}

// ---------------------------------------------------------------------------
// Kernel 2: FUSED projections + attention middle. 4 (b,n) tiles per block.
// ---------------------------------------------------------------------------
__global__ __launch_bounds__(256, 2) void fused_kernel(const float* __restrict__ inQ,
                                                       const float* __restrict__ inK,
                                                       const float* __restrict__ inV,
                                                       const float* __restrict__ w1,
                                                       const float* __restrict__ w2,
                                                       float* __restrict__ attn_out) {
    extern __shared__ __align__(16) float sm[];
    float* sA   = sm;            // Xq tf32 -> Q fp32 -> s_at2
    float* sB   = sm + 6336;     // Xk tf32 -> K fp32
    float* sC   = sm + 12672;    // Xv tf32 -> V fp32
    float* s_at = sm + 19008;    // 4608
    float* s_k2 = sm + 23616;    // 2304
    float* s_v2 = sm + 25920;    // 2304
    float* s_w1 = sm + 28224;    // 64
    float* s_w2 = sm + 28288;    // 64
    float* s_at2 = sA;

    const int tid  = threadIdx.x;
    const int lane = tid & 31, warp = tid >> 5;
    const int mw = warp >> 1, nw = warp & 1;    // valid for warp < 6
    const int bn0 = blockIdx.x * TT;
    const size_t gbase = (size_t)bn0 * (L_*D_);
    float acc[8][4];

    // ---- S0: stage all three inputs + tables ----
    stage_tf32(inQ + gbase, sA, tid);
    stage_tf32(inK + gbase, sB, tid);
    stage_tf32(inV + gbase, sC, tid);
    for (int t = tid; t < LL; t += 256) {
        const float4* sk = (const float4*)(g_K2 + t*DK);
        const float4* sv = (const float4*)(g_V2 + t*DK);
        #pragma unroll
        for (int j = 0; j < 4; j++) {
            ((float4*)(s_k2 + t*DK))[j] = sk[j];
            ((float4*)(s_v2 + t*DK))[j] = sv[j];
        }
    }
    if (tid < 64) { s_w1[tid] = w1[tid]; s_w2[tid] = w2[tid]; }
    __syncthreads();

    // ---- Q GEMM (in-place A) ----
    if (warp < 6) mma_warp((const u32t*)sA, g_Wfrag[0], mw, nw, lane, acc);
    __syncthreads();
    if (warp < 6) {
        store_warp(sA, mw, nw, lane, acc);                         // write A
        mma_warp((const u32t*)sB, g_Wfrag[1], mw, nw, lane, acc);  // read B (independent)
    }
    __syncthreads();
    if (warp < 6) {
        store_warp(sB, mw, nw, lane, acc);
        mma_warp((const u32t*)sC, g_Wfrag[2], mw, nw, lane, acc);
    }
    __syncthreads();
    if (warp < 6) store_warp(sC, mw, nw, lane, acc);
    __syncthreads();

    // ---- scores + w1 mix + leaky relu ----
    for (int idx = tid; idx < TT*LL; idx += 256) {
        int t = idx / LL, rem = idx - t*LL;
        int i = rem / L_, j = rem - i*L_;
        const float* qrow = sA + (t*L_ + i)*PITCH;
        const float* krow = sB + (t*L_ + j)*PITCH;
        const float4* k2 = (const float4*)(s_k2 + rem*DK);
        float4 r0 = k2[0], r1 = k2[1], r2 = k2[2], r3 = k2[3];
        float sc[H_];
        #pragma unroll
        for (int h = 0; h < H_; h++) {
            const float4* q4 = (const float4*)(qrow + h*DK);
            const float4* k4 = (const float4*)(krow + h*DK);
            float4 q0 = q4[0], q1 = q4[1], q2 = q4[2], q3 = q4[3];
            float4 k0 = k4[0], k1 = k4[1], k2v = k4[2], k3 = k4[3];
            float s = 0.f;
            s += q0.x*(k0.x+r0.x) + q0.y*(k0.y+r0.y) + q0.z*(k0.z+r0.z) + q0.w*(k0.w+r0.w);
            s += q1.x*(k1.x+r1.x) + q1.y*(k1.y+r1.y) + q1.z*(k1.z+r1.z) + q1.w*(k1.w+r1.w);
            s += q2.x*(k2v.x+r2.x) + q2.y*(k2v.y+r2.y) + q2.z*(k2v.z+r2.z) + q2.w*(k2v.w+r2.w);
            s += q3.x*(k3.x+r3.x) + q3.y*(k3.y+r3.y) + q3.z*(k3.z+r3.z) + q3.w*(k3.w+r3.w);
            sc[h] = s * 0.25f;
        }
        #pragma unroll
        for (int g = 0; g < H_; g++) {
            float s = 0.f;
            #pragma unroll
            for (int h = 0; h < H_; h++) s += sc[h] * s_w1[h*H_ + g];
            s_at[t*HLL + g*LL + rem] = (s > 0.f) ? s : 0.2f * s;
        }
    }
    __syncthreads();

    // ---- softmax over k: TT*96 rows of 12 ----
    for (int rowid = tid; rowid < TT*H_*L_; rowid += 256) {
        float* row = s_at + rowid * L_;
        float mx = row[0];
        #pragma unroll
        for (int j = 1; j < L_; j++) mx = fmaxf(mx, row[j]);
        float sum = 0.f;
        #pragma unroll
        for (int j = 0; j < L_; j++) { float e = __expf(row[j] - mx); row[j] = e; sum += e; }
        float inv = 1.f / sum;
        #pragma unroll
        for (int j = 0; j < L_; j++) row[j] *= inv;
    }
    __syncthreads();

    // ---- w2 mix -> s_at2 (A region; Q dead) + attn_ret write ----
    for (int idx = tid; idx < TT*LL; idx += 256) {
        int t = idx / LL, rem = idx - t*LL;
        int i = rem / L_, j = rem - i*L_;
        float a[H_];
        #pragma unroll
        for (int h = 0; h < H_; h++) a[h] = s_at[t*HLL + h*LL + rem];
        #pragma unroll
        for (int g = 0; g < H_; g++) {
            float s = 0.f;
            #pragma unroll
            for (int h = 0; h < H_; h++) s += a[h] * s_w2[h*H_ + g];
            s_at2[t*HLL + g*LL + rem] = s;
            attn_out[(size_t)i * ((size_t)BN*96) + (size_t)(bn0+t)*96 + g*L_ + j] = s;
        }
    }
    __syncthreads();

    // ---- context + BN partials (coalesced [bn][c] layout) ----
    {
        const int c = tid & 127;
        const int h = c >> 4, d = c & 15;
        #pragma unroll
        for (int tt = 0; tt < 2; tt++) {
            const int t = (tid >> 7) + 2*tt;
            float vj[L_];
            #pragma unroll
            for (int j = 0; j < L_; j++) vj[j] = sC[(t*L_ + j)*PITCH + c];
            const float* at = s_at2 + t*HLL + h*LL;
            float* ctxp = g_ctx + (size_t)(bn0 + t) * (L_*D_);
            float sum = 0.f, sq = 0.f;
            #pragma unroll
            for (int i = 0; i < L_; i++) {
                float a2 = 0.f;
                #pragma unroll
                for (int j = 0; j < L_; j++)
                    a2 = fmaf(at[i*L_ + j], vj[j] + s_v2[(i*L_ + j)*DK + d], a2);
                ctxp[i*D_ + c] = a2;
                sum += a2;
                sq = fmaf(a2, a2, sq);
            }
            g_psum  [(size_t)(bn0 + t)*D_ + c] = sum;
            g_psumsq[(size_t)(bn0 + t)*D_ + c] = sq;
        }
    }
}

// ---------------------------------------------------------------------------
// Kernel 3: finalize BN stats. 32 blocks, block b -> channels [4b, 4b+4).
// ---------------------------------------------------------------------------
__global__ void stats_kernel(const float* __restrict__ gamma, const float* __restrict__ beta) {
    __shared__ float red[8][256];
    const int tid = threadIdx.x;
    const int cb  = blockIdx.x * 4;
    float4 s  = make_float4(0.f, 0.f, 0.f, 0.f);
    float4 sq = make_float4(0.f, 0.f, 0.f, 0.f);
    for (int bn = tid; bn < BN; bn += 256) {
        float4 p = *(const float4*)(g_psum   + (size_t)bn*D_ + cb);
        float4 q = *(const float4*)(g_psumsq + (size_t)bn*D_ + cb);
        s.x += p.x; s.y += p.y; s.z += p.z; s.w += p.w;
        sq.x += q.x; sq.y += q.y; sq.z += q.z; sq.w += q.w;
    }
    red[0][tid] = s.x;  red[1][tid] = s.y;  red[2][tid] = s.z;  red[3][tid] = s.w;
    red[4][tid] = sq.x; red[5][tid] = sq.y; red[6][tid] = sq.z; red[7][tid] = sq.w;
    __syncthreads();
    for (int st = 128; st > 0; st >>= 1) {
        if (tid < st) {
            #pragma unroll
            for (int j = 0; j < 8; j++) red[j][tid] += red[j][tid + st];
        }
        __syncthreads();
    }
    if (tid < 4) {
        const float invN = 1.f / (float)ROWS;
        int c = cb + tid;
        float mean = red[tid][0] * invN;
        float var  = red[tid + 4][0] * invN - mean*mean;
        float sc = rsqrtf(var + 1e-5f) * gamma[c];
        g_scale[c] = sc;
        g_shift[c] = beta[c] - mean * sc;
    }
}

// ---------------------------------------------------------------------------
// Kernel 4: BN-apply + fc GEMM + ReLU + residual. M=32 tiles, grid=NBO.
// 8 warps: mw = warp&1 (m16x2), nw = warp>>1 (n32x4).
// ---------------------------------------------------------------------------
__global__ __launch_bounds__(256, 4) void out_kernel(const float* __restrict__ inV,
                                                     float* __restrict__ out) {
    __shared__ __align__(16) u32t s_x[MO*PITCH];
    __shared__ float s_scale[D_], s_shift[D_];
    const int tid = threadIdx.x;
    const size_t base = (size_t)blockIdx.x * MO * D_;

    if (tid < D_) { s_scale[tid] = g_scale[tid]; s_shift[tid] = g_shift[tid]; }
    __syncthreads();

    const float4* ctx4 = (const float4*)(g_ctx + base);
    const float4* sc4 = (const float4*)s_scale;
    const float4* sh4 = (const float4*)s_shift;
    for (int i = tid; i < MO*32; i += 256) {
        float4 x = ctx4[i];
        float4 sc = sc4[i & 31], sh = sh4[i & 31];
        int row = i >> 5, c4 = i & 31;
        uint4 t;
        t.x = to_tf32(x.x*sc.x + sh.x);
        t.y = to_tf32(x.y*sc.y + sh.y);
        t.z = to_tf32(x.z*sc.z + sh.z);
        t.w = to_tf32(x.w*sc.w + sh.w);
        ((uint4*)(s_x + row*PITCH))[c4] = t;
    }
    __syncthreads();

    const int lane = tid & 31, warp = tid >> 5;
    const int mw = warp & 1, nw = warp >> 1;
    const int g = lane >> 2, tig = lane & 3;

    float acc[4][4];
    #pragma unroll
    for (int nn = 0; nn < 4; nn++)
        #pragma unroll
        for (int q = 0; q < 4; q++) acc[nn][q] = 0.f;

    #pragma unroll 4
    for (int kk = 0; kk < 16; kk++) {
        u32t a[4];
        const u32t* abase = s_x + (mw*16 + g)*PITCH + kk*8 + tig;
        a[0] = abase[0];
        a[1] = abase[8*PITCH];
        a[2] = abase[4];
        a[3] = abase[8*PITCH + 4];
        const uint2* bp2 = (const uint2*)(g_Wfrag[3] + (kk*16 + nw*4)*64) + lane;
        #pragma unroll
        for (int nn = 0; nn < 4; nn++) {
            uint2 b = bp2[nn*32];
            mma_tf32(acc[nn], a, b.x, b.y);
        }
    }

    const float* vin = inV + base;
    float* dst = out + base;
    const int row = mw*16 + g;
    const int colb = nw*32 + 2*tig;
    #pragma unroll
    for (int nn = 0; nn < 4; nn++) {
        int col = colb + nn*8;
        float2 v0 = *(const float2*)(vin + (size_t)row*D_ + col);
        float2 v1 = *(const float2*)(vin + (size_t)(row+8)*D_ + col);
        float2 o0, o1;
        o0.x = fmaxf(acc[nn][0], 0.f) + v0.x;
        o0.y = fmaxf(acc[nn][1], 0.f) + v0.y;
        o1.x = fmaxf(acc[nn][2], 0.f) + v1.x;
        o1.y = fmaxf(acc[nn][3], 0.f) + v1.y;
        *(float2*)(dst + (size_t)row*D_ + col)     = o0;
        *(float2*)(dst + (size_t)(row+8)*D_ + col) = o1;
    }
}

// ---------------------------------------------------------------------------
extern "C" void kernel_launch(void* const* d_in, const int* in_sizes, int n_in,
                              void* d_out, int out_size) {
    const float* inQ   = (const float*)d_in[0];
    const float* inK   = (const float*)d_in[1];
    const float* inV   = (const float*)d_in[2];
    const float* wq_v  = (const float*)d_in[3];
    const float* wq_g  = (const float*)d_in[4];
    const float* wk_v  = (const float*)d_in[5];
    const float* wk_g  = (const float*)d_in[6];
    const float* wv_v  = (const float*)d_in[7];
    const float* wv_g  = (const float*)d_in[8];
    const float* fc_v  = (const float*)d_in[9];
    const float* fc_g  = (const float*)d_in[10];
    const float* rel_k = (const float*)d_in[11];
    const float* rel_v = (const float*)d_in[12];
    const float* w1    = (const float*)d_in[13];
    const float* w2    = (const float*)d_in[14];
    const float* gamma = (const float*)d_in[15];
    const float* beta  = (const float*)d_in[16];

    float* out      = (float*)d_out;
    float* attn_out = out + (size_t)ROWS * D_;

    const int fused_smem = 28352 * (int)sizeof(float);   // 113,408 B
    cudaFuncSetAttribute(fused_kernel, cudaFuncAttributeMaxDynamicSharedMemorySize, fused_smem);

    prep_kernel<<<5, 128>>>(wq_v, wq_g, wk_v, wk_g, wv_v, wv_g, fc_v, fc_g, rel_k, rel_v);
    fused_kernel<<<NBF, 256, fused_smem>>>(inQ, inK, inV, w1, w2, attn_out);
    stats_kernel<<<32, 256>>>(gamma, beta);
    out_kernel<<<NBO, 256>>>(inV, out);
}

// round 10
// speedup vs baseline: 1.1294x; 1.0410x over previous
#include <cuda_runtime.h>
#include <math.h>

#define B_      32
#define N_      325
#define L_      12
#define D_      128
#define H_      8
#define DK      16
#define BN      (B_*N_)        // 10400
#define ROWS    (BN*L_)        // 124800
#define MAXREL  11
#define LL      (L_*L_)        // 144
#define HLL     (H_*LL)        // 1152
#define PITCH   132
#define TT      2              // (b,n) tiles per fused block
#define MROWS   (TT*L_)        // 24 real rows (padded to 32 in smem)
#define NBF     (BN/TT)        // 5200
#define BROWS   32             // padded buffer rows
#define BUFSZ   (BROWS*PITCH)  // 4224 floats
#define MO      32             // out_kernel row-tile
#define NBO     (ROWS/MO)      // 3900

typedef unsigned int u32t;

// ---- static device scratch ----
__device__ __align__(16) u32t  g_Wfrag[4][D_*D_];   // tf32 weights in B-fragment order
__device__ __align__(16) float g_K2[LL*DK];
__device__ __align__(16) float g_V2[LL*DK];
__device__ __align__(16) float g_ctx[(size_t)ROWS*D_];
__device__ __align__(16) float g_psum[(size_t)BN*D_];    // [bn][c]
__device__ __align__(16) float g_psumsq[(size_t)BN*D_];  // [bn][c]
__device__ float g_scale[D_];
__device__ float g_shift[D_];

__device__ __forceinline__ u32t to_tf32(float x) {
    u32t t; asm("cvt.rna.tf32.f32 %0, %1;" : "=r"(t) : "f"(x)); return t;
}
__device__ __forceinline__ void mma_tf32(float c[4], const u32t a[4], u32t b0, u32t b1) {
    asm volatile("mma.sync.aligned.m16n8k8.row.col.f32.tf32.tf32.f32 "
                 "{%0,%1,%2,%3}, {%4,%5,%6,%7}, {%8,%9}, {%0,%1,%2,%3};"
                 : "+f"(c[0]), "+f"(c[1]), "+f"(c[2]), "+f"(c[3])
                 : "r"(a[0]), "r"(a[1]), "r"(a[2]), "r"(a[3]), "r"(b0), "r"(b1));
}

// ---------------------------------------------------------------------------
// Kernel 1: weight-norm -> tf32 B-fragment layout; rel-position tables
// ---------------------------------------------------------------------------
__global__ void prep_kernel(const float* __restrict__ wq_v, const float* __restrict__ wq_g,
                            const float* __restrict__ wk_v, const float* __restrict__ wk_g,
                            const float* __restrict__ wv_v, const float* __restrict__ wv_g,
                            const float* __restrict__ fc_v, const float* __restrict__ fc_g,
                            const float* __restrict__ rel_k, const float* __restrict__ rel_v) {
    int blk = blockIdx.x;
    if (blk < 4) {
        const float* v; const float* g;
        switch (blk) {
            case 0: v = wq_v; g = wq_g; break;
            case 1: v = wk_v; g = wk_g; break;
            case 2: v = wv_v; g = wv_g; break;
            default: v = fc_v; g = fc_g; break;
        }
        __shared__ float s_sc[D_];
        int r = threadIdx.x;
        float s = 0.f;
        for (int d = 0; d < D_; d++) { float x = v[r*D_ + d]; s += x*x; }
        s_sc[r] = g[r] * rsqrtf(s);
        __syncthreads();
        for (int idx = threadIdx.x; idx < D_*D_; idx += 128) {
            int rr   = idx & 1;
            int lane = (idx >> 1) & 31;
            int nn   = (idx >> 6) & 15;
            int kk   = idx >> 10;
            int k = kk*8 + (lane & 3) + 4*rr;
            int n = nn*8 + (lane >> 2);
            g_Wfrag[blk][idx] = to_tf32(v[n*D_ + k] * s_sc[n]);
        }
    } else {
        for (int t = threadIdx.x; t < LL; t += blockDim.x) {
            int q = t / L_, k = t % L_;
            int dist = max(-MAXREL, min(MAXREL, k - q));
            int row = dist + MAXREL;
            for (int d = 0; d < DK; d++) {
                g_K2[t*DK + d] = rel_k[row*DK + d];
                g_V2[t*DK + d] = rel_v[row*DK + d];
            }
        }
    }
}

// ---------------------------------------------------------------------------
// m16n32 warp-MMA over K=128 (uint2 B loads). Warp grid: mw in {0,1}, nw in 0..3.
// ---------------------------------------------------------------------------
__device__ __forceinline__ void mma_warp(const u32t* __restrict__ s_x,
                                         const u32t* __restrict__ Wf,
                                         int mw, int nw, int lane, float acc[4][4]) {
    const int g = lane >> 2, tig = lane & 3;
    #pragma unroll
    for (int nn = 0; nn < 4; nn++)
        #pragma unroll
        for (int q = 0; q < 4; q++) acc[nn][q] = 0.f;
    #pragma unroll 4
    for (int kk = 0; kk < 16; kk++) {
        u32t a[4];
        const u32t* base = s_x + (mw*16 + g)*PITCH + kk*8 + tig;
        a[0] = base[0];
        a[1] = base[8*PITCH];
        a[2] = base[4];
        a[3] = base[8*PITCH + 4];
        const uint2* bp2 = (const uint2*)(Wf + (kk*16 + nw*4)*64) + lane;
        #pragma unroll
        for (int nn = 0; nn < 4; nn++) {
            uint2 b = bp2[nn*32];
            mma_tf32(acc[nn], a, b.x, b.y);
        }
    }
}
__device__ __forceinline__ void store_warp(float* __restrict__ dst,
                                           int mw, int nw, int lane, const float acc[4][4]) {
    const int g = lane >> 2, tig = lane & 3;
    const int row = mw*16 + g;
    const int colb = nw*32 + 2*tig;
    #pragma unroll
    for (int nn = 0; nn < 4; nn++) {
        *(float2*)(dst + row*PITCH + colb + nn*8)     = make_float2(acc[nn][0], acc[nn][1]);
        *(float2*)(dst + (row+8)*PITCH + colb + nn*8) = make_float2(acc[nn][2], acc[nn][3]);
    }
}

__device__ __forceinline__ void stage_tf32(const float* __restrict__ src, float* __restrict__ dst,
                                           int tid) {
    const float4* s4 = (const float4*)src;
    for (int i = tid; i < MROWS*32; i += 256) {
        float4 x = s4[i];
        int row = i >> 5, c4 = i & 31;
        uint4 t;
        t.x = to_tf32(x.x); t.y = to_tf32(x.y); t.z = to_tf32(x.z); t.w = to_tf32(x.w);
        ((uint4*)((u32t*)dst + row*PITCH))[c4] = t;
    }
}

// ---------------------------------------------------------------------------
// Kernel 2: FUSED projections + attention middle. 2 (b,n) tiles per block,
// 3 blocks/SM, all 8 warps active in MMA.
// ---------------------------------------------------------------------------
__global__ __launch_bounds__(256, 3) void fused_kernel(const float* __restrict__ inQ,
                                                       const float* __restrict__ inK,
                                                       const float* __restrict__ inV,
                                                       const float* __restrict__ w1,
                                                       const float* __restrict__ w2,
                                                       float* __restrict__ attn_out) {
    extern __shared__ __align__(16) float sm[];
    float* sA   = sm;                 // Xq tf32 -> Q fp32 -> s_at2
    float* sB   = sm + BUFSZ;         // Xk tf32 -> K fp32
    float* sC   = sm + 2*BUFSZ;       // Xv tf32 -> V fp32
    float* s_at = sm + 3*BUFSZ;       // 2304
    float* s_w1 = sm + 3*BUFSZ + TT*HLL;        // 64
    float* s_w2 = s_w1 + 64;                    // 64
    float* s_at2 = sA;

    const int tid  = threadIdx.x;
    const int lane = tid & 31, warp = tid >> 5;
    const int mw = warp >> 2, nw = warp & 3;
    const int bn0 = blockIdx.x * TT;
    const size_t gbase = (size_t)bn0 * (L_*D_);
    float acc[4][4];

    // ---- S0: stage all three inputs + mixing weights ----
    stage_tf32(inQ + gbase, sA, tid);
    stage_tf32(inK + gbase, sB, tid);
    stage_tf32(inV + gbase, sC, tid);
    if (tid < 64) { s_w1[tid] = w1[tid]; s_w2[tid] = w2[tid]; }
    __syncthreads();

    // ---- Q GEMM (in-place A) ----
    mma_warp((const u32t*)sA, g_Wfrag[0], mw, nw, lane, acc);
    __syncthreads();
    store_warp(sA, mw, nw, lane, acc);                         // write A
    mma_warp((const u32t*)sB, g_Wfrag[1], mw, nw, lane, acc);  // read B (independent)
    __syncthreads();
    store_warp(sB, mw, nw, lane, acc);
    mma_warp((const u32t*)sC, g_Wfrag[2], mw, nw, lane, acc);
    __syncthreads();
    store_warp(sC, mw, nw, lane, acc);
    __syncthreads();

    // ---- scores + w1 mix + leaky relu (accumulate w1 on the fly) ----
    for (int idx = tid; idx < TT*LL; idx += 256) {
        int t = idx / LL, rem = idx - t*LL;
        const int i = rem / L_, j = rem - i*L_;
        const float* qrow = sA + (t*L_ + i)*PITCH;
        const float* krow = sB + (t*L_ + j)*PITCH;
        const float4* k2 = (const float4*)(g_K2 + rem*DK);
        float4 r0 = k2[0], r1 = k2[1], r2 = k2[2], r3 = k2[3];
        float out[H_];
        #pragma unroll
        for (int g2 = 0; g2 < H_; g2++) out[g2] = 0.f;
        #pragma unroll
        for (int h = 0; h < H_; h++) {
            const float4* q4 = (const float4*)(qrow + h*DK);
            const float4* k4 = (const float4*)(krow + h*DK);
            float4 q0 = q4[0], q1 = q4[1], q2 = q4[2], q3 = q4[3];
            float4 k0 = k4[0], k1 = k4[1], k2v = k4[2], k3 = k4[3];
            float s = 0.f;
            s += q0.x*(k0.x+r0.x) + q0.y*(k0.y+r0.y) + q0.z*(k0.z+r0.z) + q0.w*(k0.w+r0.w);
            s += q1.x*(k1.x+r1.x) + q1.y*(k1.y+r1.y) + q1.z*(k1.z+r1.z) + q1.w*(k1.w+r1.w);
            s += q2.x*(k2v.x+r2.x) + q2.y*(k2v.y+r2.y) + q2.z*(k2v.z+r2.z) + q2.w*(k2v.w+r2.w);
            s += q3.x*(k3.x+r3.x) + q3.y*(k3.y+r3.y) + q3.z*(k3.z+r3.z) + q3.w*(k3.w+r3.w);
            s *= 0.25f;
            #pragma unroll
            for (int g2 = 0; g2 < H_; g2++) out[g2] = fmaf(s, s_w1[h*H_ + g2], out[g2]);
        }
        #pragma unroll
        for (int g2 = 0; g2 < H_; g2++) {
            float s = out[g2];
            s_at[t*HLL + g2*LL + rem] = (s > 0.f) ? s : 0.2f * s;
        }
    }
    __syncthreads();

    // ---- softmax over k: TT*96 rows of 12 ----
    for (int rowid = tid; rowid < TT*H_*L_; rowid += 256) {
        float* row = s_at + rowid * L_;
        float mx = row[0];
        #pragma unroll
        for (int j = 1; j < L_; j++) mx = fmaxf(mx, row[j]);
        float sum = 0.f;
        #pragma unroll
        for (int j = 0; j < L_; j++) { float e = __expf(row[j] - mx); row[j] = e; sum += e; }
        float inv = 1.f / sum;
        #pragma unroll
        for (int j = 0; j < L_; j++) row[j] *= inv;
    }
    __syncthreads();

    // ---- w2 mix -> s_at2 (A region; Q dead) + attn_ret write ----
    for (int idx = tid; idx < TT*LL; idx += 256) {
        int t = idx / LL, rem = idx - t*LL;
        int i = rem / L_, j = rem - i*L_;
        float a[H_];
        #pragma unroll
        for (int h = 0; h < H_; h++) a[h] = s_at[t*HLL + h*LL + rem];
        #pragma unroll
        for (int g2 = 0; g2 < H_; g2++) {
            float s = 0.f;
            #pragma unroll
            for (int h = 0; h < H_; h++) s = fmaf(a[h], s_w2[h*H_ + g2], s);
            s_at2[t*HLL + g2*LL + rem] = s;
            attn_out[(size_t)i * ((size_t)BN*96) + (size_t)(bn0+t)*96 + g2*L_ + j] = s;
        }
    }
    __syncthreads();

    // ---- context + BN partials (coalesced [bn][c] layout) ----
    {
        const int c = tid & 127;
        const int t = tid >> 7;           // TT = 2 tiles, 128 channels each
        const int h = c >> 4, d = c & 15;
        float vj[L_];
        #pragma unroll
        for (int j = 0; j < L_; j++) vj[j] = sC[(t*L_ + j)*PITCH + c];
        const float* at = s_at2 + t*HLL + h*LL;
        float* ctxp = g_ctx + (size_t)(bn0 + t) * (L_*D_);
        float sum = 0.f, sq = 0.f;
        #pragma unroll
        for (int i = 0; i < L_; i++) {
            float a2 = 0.f;
            #pragma unroll
            for (int j = 0; j < L_; j++)
                a2 = fmaf(at[i*L_ + j], vj[j] + __ldg(g_V2 + (i*L_ + j)*DK + d), a2);
            ctxp[i*D_ + c] = a2;
            sum += a2;
            sq = fmaf(a2, a2, sq);
        }
        g_psum  [(size_t)(bn0 + t)*D_ + c] = sum;
        g_psumsq[(size_t)(bn0 + t)*D_ + c] = sq;
    }
}

// ---------------------------------------------------------------------------
// Kernel 3: finalize BN stats. 32 blocks, block b -> channels [4b, 4b+4).
// ---------------------------------------------------------------------------
__global__ void stats_kernel(const float* __restrict__ gamma, const float* __restrict__ beta) {
    __shared__ float red[8][256];
    const int tid = threadIdx.x;
    const int cb  = blockIdx.x * 4;
    float4 s  = make_float4(0.f, 0.f, 0.f, 0.f);
    float4 sq = make_float4(0.f, 0.f, 0.f, 0.f);
    for (int bn = tid; bn < BN; bn += 256) {
        float4 p = *(const float4*)(g_psum   + (size_t)bn*D_ + cb);
        float4 q = *(const float4*)(g_psumsq + (size_t)bn*D_ + cb);
        s.x += p.x; s.y += p.y; s.z += p.z; s.w += p.w;
        sq.x += q.x; sq.y += q.y; sq.z += q.z; sq.w += q.w;
    }
    red[0][tid] = s.x;  red[1][tid] = s.y;  red[2][tid] = s.z;  red[3][tid] = s.w;
    red[4][tid] = sq.x; red[5][tid] = sq.y; red[6][tid] = sq.z; red[7][tid] = sq.w;
    __syncthreads();
    for (int st = 128; st > 0; st >>= 1) {
        if (tid < st) {
            #pragma unroll
            for (int j = 0; j < 8; j++) red[j][tid] += red[j][tid + st];
        }
        __syncthreads();
    }
    if (tid < 4) {
        const float invN = 1.f / (float)ROWS;
        int c = cb + tid;
        float mean = red[tid][0] * invN;
        float var  = red[tid + 4][0] * invN - mean*mean;
        float sc = rsqrtf(var + 1e-5f) * gamma[c];
        g_scale[c] = sc;
        g_shift[c] = beta[c] - mean * sc;
    }
}

// ---------------------------------------------------------------------------
// Kernel 4: BN-apply + fc GEMM + ReLU + residual. M=32 tiles, grid=NBO.
// ---------------------------------------------------------------------------
__global__ __launch_bounds__(256, 4) void out_kernel(const float* __restrict__ inV,
                                                     float* __restrict__ out) {
    __shared__ __align__(16) u32t s_x[MO*PITCH];
    __shared__ float s_scale[D_], s_shift[D_];
    const int tid = threadIdx.x;
    const size_t base = (size_t)blockIdx.x * MO * D_;

    if (tid < D_) { s_scale[tid] = g_scale[tid]; s_shift[tid] = g_shift[tid]; }
    __syncthreads();

    const float4* ctx4 = (const float4*)(g_ctx + base);
    const float4* sc4 = (const float4*)s_scale;
    const float4* sh4 = (const float4*)s_shift;
    for (int i = tid; i < MO*32; i += 256) {
        float4 x = ctx4[i];
        float4 sc = sc4[i & 31], sh = sh4[i & 31];
        int row = i >> 5, c4 = i & 31;
        uint4 t;
        t.x = to_tf32(x.x*sc.x + sh.x);
        t.y = to_tf32(x.y*sc.y + sh.y);
        t.z = to_tf32(x.z*sc.z + sh.z);
        t.w = to_tf32(x.w*sc.w + sh.w);
        ((uint4*)(s_x + row*PITCH))[c4] = t;
    }
    __syncthreads();

    const int lane = tid & 31, warp = tid >> 5;
    const int mw = warp & 1, nw = warp >> 1;
    const int g = lane >> 2, tig = lane & 3;

    float acc[4][4];
    #pragma unroll
    for (int nn = 0; nn < 4; nn++)
        #pragma unroll
        for (int q = 0; q < 4; q++) acc[nn][q] = 0.f;

    #pragma unroll 4
    for (int kk = 0; kk < 16; kk++) {
        u32t a[4];
        const u32t* abase = s_x + (mw*16 + g)*PITCH + kk*8 + tig;
        a[0] = abase[0];
        a[1] = abase[8*PITCH];
        a[2] = abase[4];
        a[3] = abase[8*PITCH + 4];
        const uint2* bp2 = (const uint2*)(g_Wfrag[3] + (kk*16 + nw*4)*64) + lane;
        #pragma unroll
        for (int nn = 0; nn < 4; nn++) {
            uint2 b = bp2[nn*32];
            mma_tf32(acc[nn], a, b.x, b.y);
        }
    }

    const float* vin = inV + base;
    float* dst = out + base;
    const int row = mw*16 + g;
    const int colb = nw*32 + 2*tig;
    #pragma unroll
    for (int nn = 0; nn < 4; nn++) {
        int col = colb + nn*8;
        float2 v0 = *(const float2*)(vin + (size_t)row*D_ + col);
        float2 v1 = *(const float2*)(vin + (size_t)(row+8)*D_ + col);
        float2 o0, o1;
        o0.x = fmaxf(acc[nn][0], 0.f) + v0.x;
        o0.y = fmaxf(acc[nn][1], 0.f) + v0.y;
        o1.x = fmaxf(acc[nn][2], 0.f) + v1.x;
        o1.y = fmaxf(acc[nn][3], 0.f) + v1.y;
        *(float2*)(dst + (size_t)row*D_ + col)     = o0;
        *(float2*)(dst + (size_t)(row+8)*D_ + col) = o1;
    }
}

// ---------------------------------------------------------------------------
extern "C" void kernel_launch(void* const* d_in, const int* in_sizes, int n_in,
                              void* d_out, int out_size) {
    const float* inQ   = (const float*)d_in[0];
    const float* inK   = (const float*)d_in[1];
    const float* inV   = (const float*)d_in[2];
    const float* wq_v  = (const float*)d_in[3];
    const float* wq_g  = (const float*)d_in[4];
    const float* wk_v  = (const float*)d_in[5];
    const float* wk_g  = (const float*)d_in[6];
    const float* wv_v  = (const float*)d_in[7];
    const float* wv_g  = (const float*)d_in[8];
    const float* fc_v  = (const float*)d_in[9];
    const float* fc_g  = (const float*)d_in[10];
    const float* rel_k = (const float*)d_in[11];
    const float* rel_v = (const float*)d_in[12];
    const float* w1    = (const float*)d_in[13];
    const float* w2    = (const float*)d_in[14];
    const float* gamma = (const float*)d_in[15];
    const float* beta  = (const float*)d_in[16];

    float* out      = (float*)d_out;
    float* attn_out = out + (size_t)ROWS * D_;

    const int fused_smem = (3*BUFSZ + TT*HLL + 128) * (int)sizeof(float);   // 60,416 B
    cudaFuncSetAttribute(fused_kernel, cudaFuncAttributeMaxDynamicSharedMemorySize, fused_smem);

    prep_kernel<<<5, 128>>>(wq_v, wq_g, wk_v, wk_g, wv_v, wv_g, fc_v, fc_g, rel_k, rel_v);
    fused_kernel<<<NBF, 256, fused_smem>>>(inQ, inK, inV, w1, w2, attn_out);
    stats_kernel<<<32, 256>>>(gamma, beta);
    out_kernel<<<NBO, 256>>>(inV, out);
}